// round 15
// baseline (speedup 1.0000x reference)
#include <cuda_runtime.h>
#include <cuda_bf16.h>
#include <cuda_fp16.h>
#include <cstdint>

// Problem constants
#define SEQ   2048
#define BATCH 4
#define DIM   256
#define NHEAD 8
#define HDIM  32
#define M_TOT 8192          // BATCH*SEQ
#define QK_SCALE 0.17677669529663687f            // 1/sqrt(32)
#define Q_PRESCALE (QK_SCALE * 1.4426950408889634f)  // * log2(e)

// Scratch (device globals). GEMM operands stored pre-converted to bf16.
__device__ __nv_bfloat16 g_xn [M_TOT*DIM];   // bf16(LN(x))
__device__ __nv_bfloat16 g_xt [M_TOT*DIM];   // bf16(x)
__device__ __nv_bfloat16 g_att[M_TOT*DIM];   // bf16(attention out)
__device__ __nv_bfloat16 g_y  [M_TOT*DIM];   // bf16(relu FC)
__device__ float         g_z  [M_TOT*DIM];   // fp32 z (epilogue-only)
__device__ __nv_bfloat16 g_rx [M_TOT*DIM];   // bf16(r*x)
__device__ __nv_bfloat16 g_wt [768*256 + 7*256*256];  // bf16 weights
__device__ __nv_bfloat16 g_q[M_TOT*HDIM*NHEAD];
__device__ __nv_bfloat16 g_k[M_TOT*HDIM*NHEAD];
__device__ __half        g_v[M_TOT*HDIM*NHEAD];
__device__ uint32_t g_mask[BATCH*SEQ*(SEQ/32)];

// weight offsets inside g_wt
#define OFF_QKV 0
#define OFF_FC  196608
#define OFF_WZ  (OFF_FC + 65536)
#define OFF_UZ  (OFF_WZ + 65536)
#define OFF_WR  (OFF_UZ + 65536)
#define OFF_UR  (OFF_WR + 65536)
#define OFF_WG  (OFF_UR + 65536)
#define OFF_UG  (OFF_WG + 65536)
#define WT_TOT  (OFF_UG + 65536)

// ---------------------------------------------------------------------------
__device__ __forceinline__ uint32_t pack_bf16x2(float lo, float hi)
{
    uint32_t r;
    asm("cvt.rn.bf16x2.f32 %0, %1, %2;" : "=r"(r) : "f"(hi), "f"(lo));
    return r;
}
__device__ __forceinline__ uint32_t pack_f16x2(float lo, float hi)
{
    uint32_t r;
    asm("cvt.rn.f16x2.f32 %0, %1, %2;" : "=r"(r) : "f"(hi), "f"(lo));
    return r;
}
__device__ __forceinline__ uint32_t ex2_f16x2(uint32_t x)
{
    uint32_t r;
    asm("ex2.approx.f16x2 %0, %1;" : "=r"(r) : "r"(x));
    return r;
}
__device__ __forceinline__ void ldmx4(uint32_t& r0, uint32_t& r1,
                                      uint32_t& r2, uint32_t& r3, uint32_t addr)
{
    asm volatile("ldmatrix.sync.aligned.m8n8.x4.shared.b16 {%0,%1,%2,%3},[%4];"
                 : "=r"(r0), "=r"(r1), "=r"(r2), "=r"(r3) : "r"(addr));
}
__device__ __forceinline__ void cpa16(uint32_t dst, const void* src)
{
    asm volatile("cp.async.cg.shared.global [%0], [%1], 16;" :: "r"(dst), "l"(src));
}
__device__ __forceinline__ void cpa_commit()
{
    asm volatile("cp.async.commit_group;");
}
__device__ __forceinline__ void cpa_wait2()
{
    asm volatile("cp.async.wait_group 2;");
}
__device__ __forceinline__ void mma16816bf(float* d, const uint32_t* a,
                                           uint32_t b0, uint32_t b1)
{
    asm volatile("mma.sync.aligned.m16n8k16.row.col.f32.bf16.bf16.f32 "
                 "{%0,%1,%2,%3},{%4,%5,%6,%7},{%8,%9},{%0,%1,%2,%3};\n"
                 : "+f"(d[0]), "+f"(d[1]), "+f"(d[2]), "+f"(d[3])
                 : "r"(a[0]), "r"(a[1]), "r"(a[2]), "r"(a[3]),
                   "r"(b0), "r"(b1));
}
__device__ __forceinline__ void mma16816h(float* d, const uint32_t* a,
                                          uint32_t b0, uint32_t b1)
{
    asm volatile("mma.sync.aligned.m16n8k16.row.col.f32.f16.f16.f32 "
                 "{%0,%1,%2,%3},{%4,%5,%6,%7},{%8,%9},{%0,%1,%2,%3};\n"
                 : "+f"(d[0]), "+f"(d[1]), "+f"(d[2]), "+f"(d[3])
                 : "r"(a[0]), "r"(a[1]), "r"(a[2]), "r"(a[3]),
                   "r"(b0), "r"(b1));
}

// ---------------------------------------------------------------------------
__global__ void pack_adj(const int* __restrict__ adj, uint32_t* __restrict__ mask)
{
    const int idx = blockIdx.x * 256 + threadIdx.x;
    const int v = adj[idx];
    const uint32_t bal = __ballot_sync(0xffffffffu, v != 0);
    if ((threadIdx.x & 31) == 0) mask[idx >> 5] = bal;
}

// weight -> bf16 converter
__global__ void wconv(const float* __restrict__ w_qkv, const float* __restrict__ w_fc,
                      const float* __restrict__ w_z,  const float* __restrict__ u_z,
                      const float* __restrict__ w_r,  const float* __restrict__ u_r,
                      const float* __restrict__ w_g,  const float* __restrict__ u_g,
                      __nv_bfloat16* __restrict__ wt)
{
    const int idx = blockIdx.x * 256 + threadIdx.x;
    float v;
    if (idx < OFF_FC) v = w_qkv[idx];
    else {
        const int j = (idx - OFF_FC) >> 16;
        const int l = (idx - OFF_FC) & 65535;
        const float* src[7] = {w_fc, w_z, u_z, w_r, u_r, w_g, u_g};
        v = src[j][l];
    }
    wt[idx] = __float2bfloat16(v);
}

// ---------------------------------------------------------------------------
// LayerNorm -> bf16(xn), bf16(x)
// ---------------------------------------------------------------------------
__global__ void ln_kernel(const float* __restrict__ x,
                          const float* __restrict__ gamma,
                          const float* __restrict__ beta,
                          __nv_bfloat16* __restrict__ out_xn,
                          __nv_bfloat16* __restrict__ out_xt)
{
    const int row = blockIdx.x;
    const int tid = threadIdx.x;
    const float v = x[(size_t)row*DIM + tid];
    float s = v, s2 = v*v;
    #pragma unroll
    for (int o = 16; o; o >>= 1) {
        s  += __shfl_xor_sync(0xffffffffu, s,  o);
        s2 += __shfl_xor_sync(0xffffffffu, s2, o);
    }
    __shared__ float ps[8], ps2[8];
    if ((tid & 31) == 0) { ps[tid>>5] = s; ps2[tid>>5] = s2; }
    __syncthreads();
    float tot = 0.f, tot2 = 0.f;
    #pragma unroll
    for (int i = 0; i < 8; i++) { tot += ps[i]; tot2 += ps2[i]; }
    const float mu   = tot * (1.0f/DIM);
    const float var  = tot2 * (1.0f/DIM) - mu*mu;
    const float rstd = rsqrtf(var + 1e-5f);
    out_xn[(size_t)row*DIM + tid] = __float2bfloat16((v - mu) * rstd * gamma[tid] + beta[tid]);
    out_xt[(size_t)row*DIM + tid] = __float2bfloat16(v);
}

// ---------------------------------------------------------------------------
// bf16 tensor-core GEMM (round 9/13 proven config, unchanged)
// ---------------------------------------------------------------------------
enum { MODE_QKV = 0, MODE_FC = 1, MODE_ZR = 2, MODE_H = 3 };

#define AST 36
#define A_STG (128*AST)
#define B_STG (64*AST)
#define GSTAGES 4
#define GSMEM (GSTAGES*(A_STG + B_STG)*4)

__global__ void __launch_bounds__(256, 2)
gemm_tc(const __nv_bfloat16* __restrict__ A1, const __nv_bfloat16* __restrict__ A2,
        const __nv_bfloat16* __restrict__ B00, const __nv_bfloat16* __restrict__ B01,
        const __nv_bfloat16* __restrict__ B10, const __nv_bfloat16* __restrict__ B11,
        const float* __restrict__ bias,
        const float* __restrict__ X,
        const float* __restrict__ Zb,
        float* __restrict__ C,
        __nv_bfloat16* __restrict__ Cb,
        __nv_bfloat16* __restrict__ qb,
        __nv_bfloat16* __restrict__ kb,
        __half* __restrict__ vb,
        int mode, int KT)
{
    extern __shared__ uint32_t sm[];
    const int tid  = threadIdx.x;
    const int lane = tid & 31;
    const int w    = tid >> 5;
    const int wm   = w >> 1, wn = w & 1;
    const int m0   = blockIdx.y * 128;
    const int n0   = blockIdx.x * 64;
    const int half = (mode == MODE_ZR && n0 >= 256) ? 1 : 0;
    const int brow0 = n0 - (half ? 256 : 0);

    const uint32_t as_u32 = (uint32_t)__cvta_generic_to_shared(sm);
    const uint32_t bs_u32 = as_u32 + GSTAGES*A_STG*4;
    const uint32_t a_frag = as_u32 + (((wm*32 + (lane & 15))*AST + (lane >> 4)*4) << 2);
    const uint32_t b_frag = bs_u32 + (((wn*32 + (lane & 7))*AST + (lane >> 3)*4) << 2);

    const int acr = tid >> 3;
    const int acw = (tid & 7) * 8;
    float acc[8][4];
    #pragma unroll
    for (int i = 0; i < 8; i++)
        #pragma unroll
        for (int j = 0; j < 4; j++) acc[i][j] = 0.f;

    auto issue = [&](int t, int s) {
        if (t < KT) {
            const int kg    = t * 64;
            const int phase = kg >= 256;
            const int k0    = kg & 255;
            const __nv_bfloat16* Ap = phase ? A2 : A1;
            const __nv_bfloat16* Bp = half ? (phase ? B11 : B10) : (phase ? B01 : B00);
            const uint32_t asb = as_u32 + (s*A_STG << 2);
            const uint32_t bsb = bs_u32 + (s*B_STG << 2);
            #pragma unroll
            for (int it = 0; it < 4; it++) {
                const int r = acr + it*32;
                cpa16(asb + ((r*AST + (acw >> 1)) << 2),
                      Ap + (size_t)(m0 + r)*256 + k0 + acw);
            }
            #pragma unroll
            for (int it = 0; it < 2; it++) {
                const int r = acr + it*32;
                cpa16(bsb + ((r*AST + (acw >> 1)) << 2),
                      Bp + (size_t)(brow0 + r)*256 + k0 + acw);
            }
        }
        cpa_commit();
    };

    issue(0, 0);
    issue(1, 1);
    issue(2, 2);

    for (int kt = 0; kt < KT; kt++) {
        cpa_wait2();
        __syncthreads();
        issue(kt + 3, (kt + 3) & 3);

        const int s = kt & 3;
        const uint32_t aaddr = a_frag + (s*A_STG << 2);
        const uint32_t baddr = b_frag + (s*B_STG << 2);
        #pragma unroll
        for (int kh = 0; kh < 2; kh++) {
            uint32_t aF[2][2][4];
            #pragma unroll
            for (int tm = 0; tm < 2; tm++)
                #pragma unroll
                for (int kk = 0; kk < 2; kk++)
                    ldmx4(aF[tm][kk][0], aF[tm][kk][1], aF[tm][kk][2], aF[tm][kk][3],
                          aaddr + ((tm*16*AST + kh*16 + kk*8) << 2));
            uint32_t bF[4][4];
            #pragma unroll
            for (int tn = 0; tn < 4; tn++)
                ldmx4(bF[tn][0], bF[tn][1], bF[tn][2], bF[tn][3],
                      baddr + ((tn*8*AST + kh*16) << 2));
            #pragma unroll
            for (int tm = 0; tm < 2; tm++)
                #pragma unroll
                for (int tn = 0; tn < 4; tn++) {
                    mma16816bf(acc[tm*4 + tn], aF[tm][0], bF[tn][0], bF[tn][1]);
                    mma16816bf(acc[tm*4 + tn], aF[tm][1], bF[tn][2], bF[tn][3]);
                }
        }
        __syncthreads();
    }

    const int rbase = m0 + wm*32 + (lane >> 2);
    const int cbase = n0 + wn*32 + 2*(lane & 3);

    #pragma unroll
    for (int tm = 0; tm < 2; tm++) {
        #pragma unroll
        for (int tn = 0; tn < 4; tn++) {
            const float* ac = acc[tm*4 + tn];
            const int c = cbase + tn*8;
            #pragma unroll
            for (int hrow = 0; hrow < 2; hrow++) {
                const int m = rbase + tm*16 + hrow*8;
                const float v0 = ac[hrow*2], v1 = ac[hrow*2 + 1];
                if (mode == MODE_QKV) {
                    const int b_ = m >> 11, s_ = m & 2047;
                    const int h_ = c / 96, buf = (c >> 5) % 3, d_ = c & 31;
                    const size_t dst = ((size_t)((b_*NHEAD + h_)*SEQ + s_))*HDIM + d_;
                    if (buf == 2) {
                        *(uint32_t*)&vb[dst] = pack_f16x2(v0 + bias[c], v1 + bias[c+1]);
                    } else {
                        const float sc = (buf == 0) ? Q_PRESCALE : 1.0f;
                        const uint32_t pk = pack_bf16x2((v0 + bias[c])*sc,
                                                        (v1 + bias[c+1])*sc);
                        __nv_bfloat16* base = (buf == 0) ? qb : kb;
                        *(uint32_t*)&base[dst] = pk;
                    }
                } else if (mode == MODE_FC) {
                    *(uint32_t*)&Cb[(size_t)m*256 + c] =
                        pack_bf16x2(fmaxf(v0 + bias[c], 0.f),
                                    fmaxf(v1 + bias[c+1], 0.f));
                } else if (mode == MODE_ZR) {
                    if (!half) {
                        float2 o;
                        o.x = 1.f/(1.f + __expf(-(v0 + bias[c])));
                        o.y = 1.f/(1.f + __expf(-(v1 + bias[c+1])));
                        *(float2*)&C[(size_t)m*256 + c] = o;
                    } else {
                        const int nc = c - 256;
                        const float2 xv = *(const float2*)&X[(size_t)m*256 + nc];
                        *(uint32_t*)&Cb[(size_t)m*256 + nc] =
                            pack_bf16x2(xv.x / (1.f + __expf(-v0)),
                                        xv.y / (1.f + __expf(-v1)));
                    }
                } else {  // MODE_H
                    const float2 zz = *(const float2*)&Zb[(size_t)m*256 + c];
                    const float2 xv = *(const float2*)&X [(size_t)m*256 + c];
                    float2 o;
                    o.x = (1.f - zz.x)*xv.x + zz.x*tanhf(v0);
                    o.y = (1.f - zz.y)*xv.y + zz.y*tanhf(v1);
                    *(float2*)&C[(size_t)m*256 + c] = o;
                }
            }
        }
    }
}

// ---------------------------------------------------------------------------
// flash attention v6: 32 Q-rows/warp + cross-tile software pipeline:
// iteration t computes scores(t) and PV(t-1) (independent register sets),
// letting the scheduler overlap the mma->cvt->ex2 chain with PV HMMAs.
// 3 smem buffers; 2-deep global register prefetch; one sync per tile.
// ---------------------------------------------------------------------------
#define KS_STRIDE 36
#define VP_STRIDE 36
#define KS_WORDS  (64*KS_STRIDE)
#define VP_WORDS  (32*VP_STRIDE)

__global__ void __launch_bounds__(256, 1)
attn_mma(const __nv_bfloat16* __restrict__ q,
         const __nv_bfloat16* __restrict__ k,
         const __half* __restrict__ v,
         const uint32_t* __restrict__ mask,
         __nv_bfloat16* __restrict__ outp)
{
    const int tid  = threadIdx.x;
    const int lane = tid & 31;
    const int w    = tid >> 5;
    const int h    = blockIdx.y;
    const int b    = blockIdx.z;
    const int q0   = blockIdx.x * 256;

    const size_t nb = (size_t)(b*NHEAD + h) * SEQ;
    const int gr = w*32 + (lane >> 2);
    const int c2 = (lane & 3) * 2;

    __shared__ uint32_t Ks[3][KS_WORDS];
    __shared__ uint32_t Vp[3][VP_WORDS];

    uint32_t qa[2][2][4];
    {
        const __nv_bfloat16* qbase = q + (nb + q0) * HDIM;
        #pragma unroll
        for (int j = 0; j < 2; j++) {
            #pragma unroll
            for (int kt = 0; kt < 2; kt++) {
                const int r0 = gr + 16*j;
                qa[j][kt][0] = *(const uint32_t*)&qbase[(size_t)(r0    )*HDIM + kt*16 + c2    ];
                qa[j][kt][1] = *(const uint32_t*)&qbase[(size_t)(r0 + 8)*HDIM + kt*16 + c2    ];
                qa[j][kt][2] = *(const uint32_t*)&qbase[(size_t)(r0    )*HDIM + kt*16 + c2 + 8];
                qa[j][kt][3] = *(const uint32_t*)&qbase[(size_t)(r0 + 8)*HDIM + kt*16 + c2 + 8];
            }
        }
    }

    const int kn  = tid >> 2, kc  = tid & 3;
    const int vkp = tid >> 3, vd0 = (tid & 7) * 4;
    const __nv_bfloat16* kgp = k + (nb + kn   )*HDIM + kc*8;
    const __half*        vg0 = v + (nb + 2*vkp    )*HDIM + vd0;
    const __half*        vg1 = v + (nb + 2*vkp + 1)*HDIM + vd0;

    const uint32_t* mrow0 = mask + ((size_t)b*SEQ + q0 + gr) * (SEQ/32);
    const uint32_t* mrow1 = mrow0 +  8 * (SEQ/32);
    const uint32_t* mrow2 = mrow0 + 16 * (SEQ/32);
    const uint32_t* mrow3 = mrow0 + 24 * (SEQ/32);

    const uint32_t ks_smem = (uint32_t)__cvta_generic_to_shared(&Ks[0][0]);
    const uint32_t vp_smem = (uint32_t)__cvta_generic_to_shared(&Vp[0][0]);
    const uint32_t ks_lane = ks_smem + (((lane & 7)*KS_STRIDE + (lane >> 3)*4) << 2);
    const uint32_t vp_lane = vp_smem + (((lane & 7)*VP_STRIDE + (lane >> 3)*4) << 2);

    const uint32_t ones = ((lane >> 2) == 0) ? 0x3C003C00u : 0u;

    float o[2][4][4];
    #pragma unroll
    for (int j = 0; j < 2; j++)
        #pragma unroll
        for (int i = 0; i < 4; i++)
            #pragma unroll
            for (int t = 0; t < 4; t++) o[j][i][t] = 0.f;
    float o4[2][4] = {{0.f,0.f,0.f,0.f},{0.f,0.f,0.f,0.f}};

    // 2-deep global prefetch slots
    uint4 kvA, kvB;
    uint2 v0A, v1A, v0B, v1B;
    uint2 mskA[4], mskB[4];
    {
        kvA = *(const uint4*)kgp;
        v0A = *(const uint2*)vg0;
        v1A = *(const uint2*)vg1;
        mskA[0] = *(const uint2*)&mrow0[0];
        mskA[1] = *(const uint2*)&mrow1[0];
        mskA[2] = *(const uint2*)&mrow2[0];
        mskA[3] = *(const uint2*)&mrow3[0];
        const int k1 = 64*HDIM;
        kvB = *(const uint4*)(kgp + k1);
        v0B = *(const uint2*)(vg0 + k1);
        v1B = *(const uint2*)(vg1 + k1);
        mskB[0] = *(const uint2*)&mrow0[2];
        mskB[1] = *(const uint2*)&mrow1[2];
        mskB[2] = *(const uint2*)&mrow2[2];
        mskB[3] = *(const uint2*)&mrow3[2];
    }

    // two P register sets (ping-pong, statically selected by call site)
    uint32_t PA0[2][8], PA1[2][8], PB0[2][8], PB1[2][8];

    // PV for a completed tile (consumes Pr*, reads Vp buffer bufp)
    auto do_pv = [&](int bufp, uint32_t (&Pr0)[2][8], uint32_t (&Pr1)[2][8]) {
        const uint32_t vpb = vp_lane + bufp*(VP_WORDS*4);
        #pragma unroll
        for (int hf = 0; hf < 2; hf++) {
            uint32_t aA[2][4], aB[2][4];
            #pragma unroll
            for (int j = 0; j < 2; j++) {
                aA[j][0] = Pr0[j][4*hf    ]; aA[j][1] = Pr1[j][4*hf    ];
                aA[j][2] = Pr0[j][4*hf + 1]; aA[j][3] = Pr1[j][4*hf + 1];
                aB[j][0] = Pr0[j][4*hf + 2]; aB[j][1] = Pr1[j][4*hf + 2];
                aB[j][2] = Pr0[j][4*hf + 3]; aB[j][3] = Pr1[j][4*hf + 3];
                mma16816h(o4[j], aA[j], ones, ones);
                mma16816h(o4[j], aB[j], ones, ones);
            }
            #pragma unroll
            for (int dt = 0; dt < 4; dt++) {
                uint32_t vb0, vb1, vb2, vb3;
                ldmx4(vb0, vb1, vb2, vb3, vpb + dt*(8*VP_STRIDE*4) + hf*64);
                #pragma unroll
                for (int j = 0; j < 2; j++) {
                    mma16816h(o[j][dt], aA[j], vb0, vb1);
                    mma16816h(o[j][dt], aB[j], vb2, vb3);
                }
            }
        }
    };

    // one tile: stage tile kt, prefetch kt+2, scores(kt) into Pw*, PV(kt-1) from Pr*
    auto tile_body = [&](int kt, uint4& kv, uint2& vr0, uint2& vr1, uint2* msk,
                         uint32_t (&Pw0)[2][8], uint32_t (&Pw1)[2][8],
                         uint32_t (&Pr0)[2][8], uint32_t (&Pr1)[2][8]) {
        const int buf = kt % 3;

        *(uint4*)&Ks[buf][kn*KS_STRIDE + kc*4] = kv;
        Vp[buf][(vd0    )*VP_STRIDE + vkp] = __byte_perm(vr0.x, vr1.x, 0x5410);
        Vp[buf][(vd0 + 1)*VP_STRIDE + vkp] = __byte_perm(vr0.x, vr1.x, 0x7632);
        Vp[buf][(vd0 + 2)*VP_STRIDE + vkp] = __byte_perm(vr0.y, vr1.y, 0x5410);
        Vp[buf][(vd0 + 3)*VP_STRIDE + vkp] = __byte_perm(vr0.y, vr1.y, 0x7632);
        const uint2 cm0 = msk[0], cm1 = msk[1], cm2 = msk[2], cm3 = msk[3];

        if (kt + 2 < SEQ/64) {
            const int koff = (kt + 2) * 64 * HDIM;
            kv  = *(const uint4*)(kgp + koff);
            vr0 = *(const uint2*)(vg0 + koff);
            vr1 = *(const uint2*)(vg1 + koff);
            msk[0] = *(const uint2*)&mrow0[(kt + 2)*2];
            msk[1] = *(const uint2*)&mrow1[(kt + 2)*2];
            msk[2] = *(const uint2*)&mrow2[(kt + 2)*2];
            msk[3] = *(const uint2*)&mrow3[(kt + 2)*2];
        }
        __syncthreads();

        // ---- scores(kt) -> Pw ----
        const uint32_t ksb = ks_lane + buf*(KS_WORDS*4);
        #pragma unroll
        for (int nt = 0; nt < 8; nt++) {
            uint32_t kb0, kb1, kb2, kb3;
            ldmx4(kb0, kb1, kb2, kb3, ksb + nt*(8*KS_STRIDE*4));
            const int sh = ((nt & 3) * 8) + c2;
            {
                float s[4] = {0.f, 0.f, 0.f, 0.f};
                mma16816bf(s, qa[0][0], kb0, kb1);
                mma16816bf(s, qa[0][1], kb2, kb3);
                const uint32_t ulo = ((nt < 4) ? cm0.x : cm0.y) >> sh;
                const uint32_t uhi = ((nt < 4) ? cm1.x : cm1.y) >> sh;
                const uint32_t mwlo = (ulo & 1u)*0xFFFFu + (ulo & 2u)*0x7FFF8000u;
                const uint32_t mwhi = (uhi & 1u)*0xFFFFu + (uhi & 2u)*0x7FFF8000u;
                Pw0[0][nt] = ex2_f16x2(pack_f16x2(s[0], s[1])) & mwlo;
                Pw1[0][nt] = ex2_f16x2(pack_f16x2(s[2], s[3])) & mwhi;
            }
            {
                float s[4] = {0.f, 0.f, 0.f, 0.f};
                mma16816bf(s, qa[1][0], kb0, kb1);
                mma16816bf(s, qa[1][1], kb2, kb3);
                const uint32_t ulo = ((nt < 4) ? cm2.x : cm2.y) >> sh;
                const uint32_t uhi = ((nt < 4) ? cm3.x : cm3.y) >> sh;
                const uint32_t mwlo = (ulo & 1u)*0xFFFFu + (ulo & 2u)*0x7FFF8000u;
                const uint32_t mwhi = (uhi & 1u)*0xFFFFu + (uhi & 2u)*0x7FFF8000u;
                Pw0[1][nt] = ex2_f16x2(pack_f16x2(s[0], s[1])) & mwlo;
                Pw1[1][nt] = ex2_f16x2(pack_f16x2(s[2], s[3])) & mwhi;
            }
        }

        // ---- PV(kt-1) from Pr, overlapped with the score chain above ----
        if (kt > 0)
            do_pv((kt + 2) % 3, Pr0, Pr1);
    };

    for (int kt = 0; kt < SEQ/64; kt += 2) {
        tile_body(kt,     kvA, v0A, v1A, mskA, PA0, PA1, PB0, PB1);
        tile_body(kt + 1, kvB, v0B, v1B, mskB, PB0, PB1, PA0, PA1);
    }
    // drain: PV for the final tile (SEQ/64-1, odd -> P in B set)
    do_pv((SEQ/64 - 1) % 3, PB0, PB1);

    const int n_  = b*NHEAD + h;
    const int bo  = n_ & 3;
    const int hp  = n_ >> 2;
    #pragma unroll
    for (int j = 0; j < 2; j++) {
        const float sum_lo = __shfl_sync(0xffffffffu, o4[j][0], lane & ~3);
        const float sum_hi = __shfl_sync(0xffffffffu, o4[j][2], lane & ~3);
        const float inv_lo = 1.f / sum_lo;
        const float inv_hi = 1.f / sum_hi;
        #pragma unroll
        for (int dt = 0; dt < 4; dt++) {
            const size_t base = ((size_t)(bo*SEQ + q0 + gr + 16*j))*DIM
                                + hp*HDIM + dt*8 + c2;
            *(uint32_t*)&outp[base] =
                pack_bf16x2(o[j][dt][0]*inv_lo, o[j][dt][1]*inv_lo);
            *(uint32_t*)&outp[base + 8*DIM] =
                pack_bf16x2(o[j][dt][2]*inv_hi, o[j][dt][3]*inv_hi);
        }
    }
}

// ---------------------------------------------------------------------------
extern "C" void kernel_launch(void* const* d_in, const int* in_sizes, int n_in,
                              void* d_out, int out_size)
{
    const float* x     = (const float*)d_in[0];
    const int*   adj   = (const int*)  d_in[1];
    const float* w_qkv = (const float*)d_in[2];
    const float* b_qkv = (const float*)d_in[3];
    const float* ln_g  = (const float*)d_in[4];
    const float* ln_b  = (const float*)d_in[5];
    const float* w_fc  = (const float*)d_in[6];
    const float* b_fc  = (const float*)d_in[7];
    const float* w_z   = (const float*)d_in[8];
    const float* b_z   = (const float*)d_in[9];
    const float* u_z   = (const float*)d_in[10];
    const float* w_r   = (const float*)d_in[11];
    const float* u_r   = (const float*)d_in[12];
    const float* w_g   = (const float*)d_in[13];
    const float* u_g   = (const float*)d_in[14];
    float* out = (float*)d_out;

    __nv_bfloat16 *xn, *xt, *att, *y, *rx, *wt, *qb, *kb;
    float *z;
    __half *vb;
    uint32_t *mask;
    cudaGetSymbolAddress((void**)&xn,   g_xn);
    cudaGetSymbolAddress((void**)&xt,   g_xt);
    cudaGetSymbolAddress((void**)&att,  g_att);
    cudaGetSymbolAddress((void**)&y,    g_y);
    cudaGetSymbolAddress((void**)&z,    g_z);
    cudaGetSymbolAddress((void**)&rx,   g_rx);
    cudaGetSymbolAddress((void**)&wt,   g_wt);
    cudaGetSymbolAddress((void**)&qb,   g_q);
    cudaGetSymbolAddress((void**)&kb,   g_k);
    cudaGetSymbolAddress((void**)&vb,   g_v);
    cudaGetSymbolAddress((void**)&mask, g_mask);

    static cudaStream_t s2 = nullptr;
    static cudaEvent_t evFork = nullptr, evW = nullptr, evPack = nullptr;
    if (!s2) {
        cudaStreamCreateWithFlags(&s2, cudaStreamNonBlocking);
        cudaEventCreateWithFlags(&evFork, cudaEventDisableTiming);
        cudaEventCreateWithFlags(&evW,    cudaEventDisableTiming);
        cudaEventCreateWithFlags(&evPack, cudaEventDisableTiming);
        cudaFuncSetAttribute(gemm_tc, cudaFuncAttributeMaxDynamicSharedMemorySize, GSMEM);
    }

    // fork side stream: wconv (needed by QKV) then pack_adj (needed by attn)
    cudaEventRecord(evFork, 0);
    cudaStreamWaitEvent(s2, evFork, 0);
    wconv<<<WT_TOT/256, 256, 0, s2>>>(w_qkv, w_fc, w_z, u_z, w_r, u_r, w_g, u_g, wt);
    cudaEventRecord(evW, s2);
    pack_adj<<<BATCH*SEQ*SEQ/256, 256, 0, s2>>>(adj, mask);
    cudaEventRecord(evPack, s2);

    // main stream: LN runs concurrently with wconv
    ln_kernel<<<M_TOT, 256>>>(x, ln_g, ln_b, xn, xt);
    cudaStreamWaitEvent(0, evW, 0);
    // QKV -> q/k/v
    gemm_tc<<<dim3(12, 64), 256, GSMEM>>>(xn, nullptr, wt + OFF_QKV, nullptr,
                                          nullptr, nullptr, b_qkv, nullptr, nullptr,
                                          nullptr, nullptr, qb, kb, vb, MODE_QKV, 4);
    cudaStreamWaitEvent(0, evPack, 0);
    // flash attention (pipelined scores/PV) -> bf16 att
    attn_mma<<<dim3(SEQ/256, NHEAD, BATCH), 256>>>(qb, kb, vb, mask, att);
    // FC + ReLU -> bf16 y
    gemm_tc<<<dim3(4, 64), 256, GSMEM>>>(att, nullptr, wt + OFF_FC, nullptr,
                                         nullptr, nullptr, b_fc, nullptr, nullptr,
                                         nullptr, y, nullptr, nullptr, nullptr, MODE_FC, 4);
    // fused ZR -> fp32 z, bf16 rx
    gemm_tc<<<dim3(8, 64), 256, GSMEM>>>(y, xt, wt + OFF_WZ, wt + OFF_UZ,
                                         wt + OFF_WR, wt + OFF_UR, b_z, x, nullptr,
                                         z, rx, nullptr, nullptr, nullptr, MODE_ZR, 8);
    // H -> fp32 out
    gemm_tc<<<dim3(4, 64), 256, GSMEM>>>(y, rx, wt + OFF_WG, wt + OFF_UG,
                                         nullptr, nullptr, nullptr, x, z,
                                         out, nullptr, nullptr, nullptr, nullptr, MODE_H, 8);
}

// round 16
// speedup vs baseline: 1.0158x; 1.0158x over previous
#include <cuda_runtime.h>
#include <cuda_bf16.h>
#include <cuda_fp16.h>
#include <cstdint>

// Problem constants
#define SEQ   2048
#define BATCH 4
#define DIM   256
#define NHEAD 8
#define HDIM  32
#define M_TOT 8192          // BATCH*SEQ
#define QK_SCALE 0.17677669529663687f            // 1/sqrt(32)
#define Q_PRESCALE (QK_SCALE * 1.4426950408889634f)  // * log2(e)

// Scratch (device globals). GEMM operands stored pre-converted to bf16.
__device__ __nv_bfloat16 g_xn [M_TOT*DIM];   // bf16(LN(x))
__device__ __nv_bfloat16 g_xt [M_TOT*DIM];   // bf16(x)
__device__ __nv_bfloat16 g_att[M_TOT*DIM];   // bf16(attention out)
__device__ __nv_bfloat16 g_y  [M_TOT*DIM];   // bf16(relu FC)
__device__ float         g_z  [M_TOT*DIM];   // fp32 z (epilogue-only)
__device__ __nv_bfloat16 g_rx [M_TOT*DIM];   // bf16(r*x)
__device__ __nv_bfloat16 g_wt [768*256 + 7*256*256];  // bf16 weights
__device__ __nv_bfloat16 g_q[M_TOT*HDIM*NHEAD];
__device__ __nv_bfloat16 g_k[M_TOT*HDIM*NHEAD];
__device__ __half        g_v[M_TOT*HDIM*NHEAD];
__device__ uint32_t g_mask[BATCH*SEQ*(SEQ/32)];

// weight offsets inside g_wt
#define OFF_QKV 0
#define OFF_FC  196608
#define OFF_WZ  (OFF_FC + 65536)
#define OFF_UZ  (OFF_WZ + 65536)
#define OFF_WR  (OFF_UZ + 65536)
#define OFF_UR  (OFF_WR + 65536)
#define OFF_WG  (OFF_UR + 65536)
#define OFF_UG  (OFF_WG + 65536)
#define WT_TOT  (OFF_UG + 65536)

// preamble grid layout: [0, NPACK) pack_adj, [NPACK, NPACK+NWC) wconv, rest LN
#define NPACK (BATCH*SEQ*SEQ/256)   // 65536
#define NWC   (WT_TOT/256)          // 2560
#define NLN   M_TOT                 // 8192
#define NPRE  (NPACK + NWC + NLN)

// ---------------------------------------------------------------------------
__device__ __forceinline__ uint32_t pack_bf16x2(float lo, float hi)
{
    uint32_t r;
    asm("cvt.rn.bf16x2.f32 %0, %1, %2;" : "=r"(r) : "f"(hi), "f"(lo));
    return r;
}
__device__ __forceinline__ uint32_t pack_f16x2(float lo, float hi)
{
    uint32_t r;
    asm("cvt.rn.f16x2.f32 %0, %1, %2;" : "=r"(r) : "f"(hi), "f"(lo));
    return r;
}
__device__ __forceinline__ uint32_t ex2_f16x2(uint32_t x)
{
    uint32_t r;
    asm("ex2.approx.f16x2 %0, %1;" : "=r"(r) : "r"(x));
    return r;
}
__device__ __forceinline__ void ldmx4(uint32_t& r0, uint32_t& r1,
                                      uint32_t& r2, uint32_t& r3, uint32_t addr)
{
    asm volatile("ldmatrix.sync.aligned.m8n8.x4.shared.b16 {%0,%1,%2,%3},[%4];"
                 : "=r"(r0), "=r"(r1), "=r"(r2), "=r"(r3) : "r"(addr));
}
__device__ __forceinline__ void cpa16(uint32_t dst, const void* src)
{
    asm volatile("cp.async.cg.shared.global [%0], [%1], 16;" :: "r"(dst), "l"(src));
}
__device__ __forceinline__ void cpa_commit()
{
    asm volatile("cp.async.commit_group;");
}
__device__ __forceinline__ void cpa_wait2()
{
    asm volatile("cp.async.wait_group 2;");
}
__device__ __forceinline__ void mma16816bf(float* d, const uint32_t* a,
                                           uint32_t b0, uint32_t b1)
{
    asm volatile("mma.sync.aligned.m16n8k16.row.col.f32.bf16.bf16.f32 "
                 "{%0,%1,%2,%3},{%4,%5,%6,%7},{%8,%9},{%0,%1,%2,%3};\n"
                 : "+f"(d[0]), "+f"(d[1]), "+f"(d[2]), "+f"(d[3])
                 : "r"(a[0]), "r"(a[1]), "r"(a[2]), "r"(a[3]),
                   "r"(b0), "r"(b1));
}
__device__ __forceinline__ void mma16816h(float* d, const uint32_t* a,
                                          uint32_t b0, uint32_t b1)
{
    asm volatile("mma.sync.aligned.m16n8k16.row.col.f32.f16.f16.f32 "
                 "{%0,%1,%2,%3},{%4,%5,%6,%7},{%8,%9},{%0,%1,%2,%3};\n"
                 : "+f"(d[0]), "+f"(d[1]), "+f"(d[2]), "+f"(d[3])
                 : "r"(a[0]), "r"(a[1]), "r"(a[2]), "r"(a[3]),
                   "r"(b0), "r"(b1));
}

// ---------------------------------------------------------------------------
// fused preamble: pack_adj + wconv + LN in one launch (independent work).
// pack_adj blocks come first (longest component starts immediately).
// ---------------------------------------------------------------------------
__global__ void __launch_bounds__(256)
preamble(const int* __restrict__ adj, uint32_t* __restrict__ mask,
         const float* __restrict__ w_qkv, const float* __restrict__ w_fc,
         const float* __restrict__ w_z,  const float* __restrict__ u_z,
         const float* __restrict__ w_r,  const float* __restrict__ u_r,
         const float* __restrict__ w_g,  const float* __restrict__ u_g,
         __nv_bfloat16* __restrict__ wt,
         const float* __restrict__ x,
         const float* __restrict__ gamma,
         const float* __restrict__ beta,
         __nv_bfloat16* __restrict__ out_xn,
         __nv_bfloat16* __restrict__ out_xt)
{
    const int blk = blockIdx.x;
    const int tid = threadIdx.x;

    if (blk < NPACK) {
        // ---- adjacency -> bitmask ----
        const int idx = blk * 256 + tid;
        const int v = adj[idx];
        const uint32_t bal = __ballot_sync(0xffffffffu, v != 0);
        if ((tid & 31) == 0) mask[idx >> 5] = bal;
        return;
    }
    if (blk < NPACK + NWC) {
        // ---- weights -> bf16 ----
        const int idx = (blk - NPACK) * 256 + tid;
        float v;
        if (idx < OFF_FC) v = w_qkv[idx];
        else {
            const int j = (idx - OFF_FC) >> 16;
            const int l = (idx - OFF_FC) & 65535;
            const float* src[7] = {w_fc, w_z, u_z, w_r, u_r, w_g, u_g};
            v = src[j][l];
        }
        wt[idx] = __float2bfloat16(v);
        return;
    }
    // ---- LayerNorm (one block per row) ----
    {
        const int row = blk - NPACK - NWC;
        const float v = x[(size_t)row*DIM + tid];
        float s = v, s2 = v*v;
        #pragma unroll
        for (int o = 16; o; o >>= 1) {
            s  += __shfl_xor_sync(0xffffffffu, s,  o);
            s2 += __shfl_xor_sync(0xffffffffu, s2, o);
        }
        __shared__ float ps[8], ps2[8];
        if ((tid & 31) == 0) { ps[tid>>5] = s; ps2[tid>>5] = s2; }
        __syncthreads();
        float tot = 0.f, tot2 = 0.f;
        #pragma unroll
        for (int i = 0; i < 8; i++) { tot += ps[i]; tot2 += ps2[i]; }
        const float mu   = tot * (1.0f/DIM);
        const float var  = tot2 * (1.0f/DIM) - mu*mu;
        const float rstd = rsqrtf(var + 1e-5f);
        out_xn[(size_t)row*DIM + tid] =
            __float2bfloat16((v - mu) * rstd * gamma[tid] + beta[tid]);
        out_xt[(size_t)row*DIM + tid] = __float2bfloat16(v);
    }
}

// ---------------------------------------------------------------------------
// bf16 tensor-core GEMM (round 9/13 proven config, unchanged)
// ---------------------------------------------------------------------------
enum { MODE_QKV = 0, MODE_FC = 1, MODE_ZR = 2, MODE_H = 3 };

#define AST 36
#define A_STG (128*AST)
#define B_STG (64*AST)
#define GSTAGES 4
#define GSMEM (GSTAGES*(A_STG + B_STG)*4)

__global__ void __launch_bounds__(256, 2)
gemm_tc(const __nv_bfloat16* __restrict__ A1, const __nv_bfloat16* __restrict__ A2,
        const __nv_bfloat16* __restrict__ B00, const __nv_bfloat16* __restrict__ B01,
        const __nv_bfloat16* __restrict__ B10, const __nv_bfloat16* __restrict__ B11,
        const float* __restrict__ bias,
        const float* __restrict__ X,
        const float* __restrict__ Zb,
        float* __restrict__ C,
        __nv_bfloat16* __restrict__ Cb,
        __nv_bfloat16* __restrict__ qb,
        __nv_bfloat16* __restrict__ kb,
        __half* __restrict__ vb,
        int mode, int KT)
{
    extern __shared__ uint32_t sm[];
    const int tid  = threadIdx.x;
    const int lane = tid & 31;
    const int w    = tid >> 5;
    const int wm   = w >> 1, wn = w & 1;
    const int m0   = blockIdx.y * 128;
    const int n0   = blockIdx.x * 64;
    const int half = (mode == MODE_ZR && n0 >= 256) ? 1 : 0;
    const int brow0 = n0 - (half ? 256 : 0);

    const uint32_t as_u32 = (uint32_t)__cvta_generic_to_shared(sm);
    const uint32_t bs_u32 = as_u32 + GSTAGES*A_STG*4;
    const uint32_t a_frag = as_u32 + (((wm*32 + (lane & 15))*AST + (lane >> 4)*4) << 2);
    const uint32_t b_frag = bs_u32 + (((wn*32 + (lane & 7))*AST + (lane >> 3)*4) << 2);

    const int acr = tid >> 3;
    const int acw = (tid & 7) * 8;
    float acc[8][4];
    #pragma unroll
    for (int i = 0; i < 8; i++)
        #pragma unroll
        for (int j = 0; j < 4; j++) acc[i][j] = 0.f;

    auto issue = [&](int t, int s) {
        if (t < KT) {
            const int kg    = t * 64;
            const int phase = kg >= 256;
            const int k0    = kg & 255;
            const __nv_bfloat16* Ap = phase ? A2 : A1;
            const __nv_bfloat16* Bp = half ? (phase ? B11 : B10) : (phase ? B01 : B00);
            const uint32_t asb = as_u32 + (s*A_STG << 2);
            const uint32_t bsb = bs_u32 + (s*B_STG << 2);
            #pragma unroll
            for (int it = 0; it < 4; it++) {
                const int r = acr + it*32;
                cpa16(asb + ((r*AST + (acw >> 1)) << 2),
                      Ap + (size_t)(m0 + r)*256 + k0 + acw);
            }
            #pragma unroll
            for (int it = 0; it < 2; it++) {
                const int r = acr + it*32;
                cpa16(bsb + ((r*AST + (acw >> 1)) << 2),
                      Bp + (size_t)(brow0 + r)*256 + k0 + acw);
            }
        }
        cpa_commit();
    };

    issue(0, 0);
    issue(1, 1);
    issue(2, 2);

    for (int kt = 0; kt < KT; kt++) {
        cpa_wait2();
        __syncthreads();
        issue(kt + 3, (kt + 3) & 3);

        const int s = kt & 3;
        const uint32_t aaddr = a_frag + (s*A_STG << 2);
        const uint32_t baddr = b_frag + (s*B_STG << 2);
        #pragma unroll
        for (int kh = 0; kh < 2; kh++) {
            uint32_t aF[2][2][4];
            #pragma unroll
            for (int tm = 0; tm < 2; tm++)
                #pragma unroll
                for (int kk = 0; kk < 2; kk++)
                    ldmx4(aF[tm][kk][0], aF[tm][kk][1], aF[tm][kk][2], aF[tm][kk][3],
                          aaddr + ((tm*16*AST + kh*16 + kk*8) << 2));
            uint32_t bF[4][4];
            #pragma unroll
            for (int tn = 0; tn < 4; tn++)
                ldmx4(bF[tn][0], bF[tn][1], bF[tn][2], bF[tn][3],
                      baddr + ((tn*8*AST + kh*16) << 2));
            #pragma unroll
            for (int tm = 0; tm < 2; tm++)
                #pragma unroll
                for (int tn = 0; tn < 4; tn++) {
                    mma16816bf(acc[tm*4 + tn], aF[tm][0], bF[tn][0], bF[tn][1]);
                    mma16816bf(acc[tm*4 + tn], aF[tm][1], bF[tn][2], bF[tn][3]);
                }
        }
        __syncthreads();
    }

    const int rbase = m0 + wm*32 + (lane >> 2);
    const int cbase = n0 + wn*32 + 2*(lane & 3);

    #pragma unroll
    for (int tm = 0; tm < 2; tm++) {
        #pragma unroll
        for (int tn = 0; tn < 4; tn++) {
            const float* ac = acc[tm*4 + tn];
            const int c = cbase + tn*8;
            #pragma unroll
            for (int hrow = 0; hrow < 2; hrow++) {
                const int m = rbase + tm*16 + hrow*8;
                const float v0 = ac[hrow*2], v1 = ac[hrow*2 + 1];
                if (mode == MODE_QKV) {
                    const int b_ = m >> 11, s_ = m & 2047;
                    const int h_ = c / 96, buf = (c >> 5) % 3, d_ = c & 31;
                    const size_t dst = ((size_t)((b_*NHEAD + h_)*SEQ + s_))*HDIM + d_;
                    if (buf == 2) {
                        *(uint32_t*)&vb[dst] = pack_f16x2(v0 + bias[c], v1 + bias[c+1]);
                    } else {
                        const float sc = (buf == 0) ? Q_PRESCALE : 1.0f;
                        const uint32_t pk = pack_bf16x2((v0 + bias[c])*sc,
                                                        (v1 + bias[c+1])*sc);
                        __nv_bfloat16* base = (buf == 0) ? qb : kb;
                        *(uint32_t*)&base[dst] = pk;
                    }
                } else if (mode == MODE_FC) {
                    *(uint32_t*)&Cb[(size_t)m*256 + c] =
                        pack_bf16x2(fmaxf(v0 + bias[c], 0.f),
                                    fmaxf(v1 + bias[c+1], 0.f));
                } else if (mode == MODE_ZR) {
                    if (!half) {
                        float2 o;
                        o.x = 1.f/(1.f + __expf(-(v0 + bias[c])));
                        o.y = 1.f/(1.f + __expf(-(v1 + bias[c+1])));
                        *(float2*)&C[(size_t)m*256 + c] = o;
                    } else {
                        const int nc = c - 256;
                        const float2 xv = *(const float2*)&X[(size_t)m*256 + nc];
                        *(uint32_t*)&Cb[(size_t)m*256 + nc] =
                            pack_bf16x2(xv.x / (1.f + __expf(-v0)),
                                        xv.y / (1.f + __expf(-v1)));
                    }
                } else {  // MODE_H
                    const float2 zz = *(const float2*)&Zb[(size_t)m*256 + c];
                    const float2 xv = *(const float2*)&X [(size_t)m*256 + c];
                    float2 o;
                    o.x = (1.f - zz.x)*xv.x + zz.x*tanhf(v0);
                    o.y = (1.f - zz.y)*xv.y + zz.y*tanhf(v1);
                    *(float2*)&C[(size_t)m*256 + c] = o;
                }
            }
        }
    }
}

// ---------------------------------------------------------------------------
// flash attention (round 13 design: 32 Q-rows/warp, 2-deep prefetch,
// packed fp16 ex2 softmax, ones-column row sums)
// ---------------------------------------------------------------------------
#define KS_STRIDE 36
#define VP_STRIDE 36
#define KS_WORDS  (64*KS_STRIDE)
#define VP_WORDS  (32*VP_STRIDE)

__global__ void __launch_bounds__(256, 1)
attn_mma(const __nv_bfloat16* __restrict__ q,
         const __nv_bfloat16* __restrict__ k,
         const __half* __restrict__ v,
         const uint32_t* __restrict__ mask,
         __nv_bfloat16* __restrict__ outp)
{
    const int tid  = threadIdx.x;
    const int lane = tid & 31;
    const int w    = tid >> 5;
    const int h    = blockIdx.y;
    const int b    = blockIdx.z;
    const int q0   = blockIdx.x * 256;

    const size_t nb = (size_t)(b*NHEAD + h) * SEQ;
    const int gr = w*32 + (lane >> 2);
    const int c2 = (lane & 3) * 2;

    __shared__ uint32_t Ks[2][KS_WORDS];
    __shared__ uint32_t Vp[2][VP_WORDS];

    uint32_t qa[2][2][4];
    {
        const __nv_bfloat16* qbase = q + (nb + q0) * HDIM;
        #pragma unroll
        for (int j = 0; j < 2; j++) {
            #pragma unroll
            for (int kt = 0; kt < 2; kt++) {
                const int r0 = gr + 16*j;
                qa[j][kt][0] = *(const uint32_t*)&qbase[(size_t)(r0    )*HDIM + kt*16 + c2    ];
                qa[j][kt][1] = *(const uint32_t*)&qbase[(size_t)(r0 + 8)*HDIM + kt*16 + c2    ];
                qa[j][kt][2] = *(const uint32_t*)&qbase[(size_t)(r0    )*HDIM + kt*16 + c2 + 8];
                qa[j][kt][3] = *(const uint32_t*)&qbase[(size_t)(r0 + 8)*HDIM + kt*16 + c2 + 8];
            }
        }
    }

    const int kn  = tid >> 2, kc  = tid & 3;
    const int vkp = tid >> 3, vd0 = (tid & 7) * 4;
    const __nv_bfloat16* kgp = k + (nb + kn   )*HDIM + kc*8;
    const __half*        vg0 = v + (nb + 2*vkp    )*HDIM + vd0;
    const __half*        vg1 = v + (nb + 2*vkp + 1)*HDIM + vd0;

    const uint32_t* mrow0 = mask + ((size_t)b*SEQ + q0 + gr) * (SEQ/32);
    const uint32_t* mrow1 = mrow0 +  8 * (SEQ/32);
    const uint32_t* mrow2 = mrow0 + 16 * (SEQ/32);
    const uint32_t* mrow3 = mrow0 + 24 * (SEQ/32);

    const uint32_t ks_smem = (uint32_t)__cvta_generic_to_shared(&Ks[0][0]);
    const uint32_t vp_smem = (uint32_t)__cvta_generic_to_shared(&Vp[0][0]);
    const uint32_t ks_lane = ks_smem + (((lane & 7)*KS_STRIDE + (lane >> 3)*4) << 2);
    const uint32_t vp_lane = vp_smem + (((lane & 7)*VP_STRIDE + (lane >> 3)*4) << 2);

    const uint32_t ones = ((lane >> 2) == 0) ? 0x3C003C00u : 0u;

    float o[2][4][4];
    #pragma unroll
    for (int j = 0; j < 2; j++)
        #pragma unroll
        for (int i = 0; i < 4; i++)
            #pragma unroll
            for (int t = 0; t < 4; t++) o[j][i][t] = 0.f;
    float o4[2][4] = {{0.f,0.f,0.f,0.f},{0.f,0.f,0.f,0.f}};

    uint4 kvA, kvB;
    uint2 v0A, v1A, v0B, v1B;
    uint2 mskA[4], mskB[4];
    {
        kvA = *(const uint4*)kgp;
        v0A = *(const uint2*)vg0;
        v1A = *(const uint2*)vg1;
        mskA[0] = *(const uint2*)&mrow0[0];
        mskA[1] = *(const uint2*)&mrow1[0];
        mskA[2] = *(const uint2*)&mrow2[0];
        mskA[3] = *(const uint2*)&mrow3[0];
        const int k1 = 64*HDIM;
        kvB = *(const uint4*)(kgp + k1);
        v0B = *(const uint2*)(vg0 + k1);
        v1B = *(const uint2*)(vg1 + k1);
        mskB[0] = *(const uint2*)&mrow0[2];
        mskB[1] = *(const uint2*)&mrow1[2];
        mskB[2] = *(const uint2*)&mrow2[2];
        mskB[3] = *(const uint2*)&mrow3[2];
    }

    auto tile_body = [&](int kt, uint4& kv, uint2& vr0, uint2& vr1, uint2* msk) {
        const int buf = kt & 1;

        *(uint4*)&Ks[buf][kn*KS_STRIDE + kc*4] = kv;
        Vp[buf][(vd0    )*VP_STRIDE + vkp] = __byte_perm(vr0.x, vr1.x, 0x5410);
        Vp[buf][(vd0 + 1)*VP_STRIDE + vkp] = __byte_perm(vr0.x, vr1.x, 0x7632);
        Vp[buf][(vd0 + 2)*VP_STRIDE + vkp] = __byte_perm(vr0.y, vr1.y, 0x5410);
        Vp[buf][(vd0 + 3)*VP_STRIDE + vkp] = __byte_perm(vr0.y, vr1.y, 0x7632);
        const uint2 cm0 = msk[0], cm1 = msk[1], cm2 = msk[2], cm3 = msk[3];

        if (kt + 2 < SEQ/64) {
            const int koff = (kt + 2) * 64 * HDIM;
            kv  = *(const uint4*)(kgp + koff);
            vr0 = *(const uint2*)(vg0 + koff);
            vr1 = *(const uint2*)(vg1 + koff);
            msk[0] = *(const uint2*)&mrow0[(kt + 2)*2];
            msk[1] = *(const uint2*)&mrow1[(kt + 2)*2];
            msk[2] = *(const uint2*)&mrow2[(kt + 2)*2];
            msk[3] = *(const uint2*)&mrow3[(kt + 2)*2];
        }
        __syncthreads();

        const uint32_t ksb = ks_lane + buf*(KS_WORDS*4);
        uint32_t P0[2][8], P1[2][8];
        #pragma unroll
        for (int nt = 0; nt < 8; nt++) {
            uint32_t kb0, kb1, kb2, kb3;
            ldmx4(kb0, kb1, kb2, kb3, ksb + nt*(8*KS_STRIDE*4));
            const int sh = ((nt & 3) * 8) + c2;
            {
                float s[4] = {0.f, 0.f, 0.f, 0.f};
                mma16816bf(s, qa[0][0], kb0, kb1);
                mma16816bf(s, qa[0][1], kb2, kb3);
                const uint32_t ulo = ((nt < 4) ? cm0.x : cm0.y) >> sh;
                const uint32_t uhi = ((nt < 4) ? cm1.x : cm1.y) >> sh;
                const uint32_t mwlo = (ulo & 1u)*0xFFFFu + (ulo & 2u)*0x7FFF8000u;
                const uint32_t mwhi = (uhi & 1u)*0xFFFFu + (uhi & 2u)*0x7FFF8000u;
                P0[0][nt] = ex2_f16x2(pack_f16x2(s[0], s[1])) & mwlo;
                P1[0][nt] = ex2_f16x2(pack_f16x2(s[2], s[3])) & mwhi;
            }
            {
                float s[4] = {0.f, 0.f, 0.f, 0.f};
                mma16816bf(s, qa[1][0], kb0, kb1);
                mma16816bf(s, qa[1][1], kb2, kb3);
                const uint32_t ulo = ((nt < 4) ? cm2.x : cm2.y) >> sh;
                const uint32_t uhi = ((nt < 4) ? cm3.x : cm3.y) >> sh;
                const uint32_t mwlo = (ulo & 1u)*0xFFFFu + (ulo & 2u)*0x7FFF8000u;
                const uint32_t mwhi = (uhi & 1u)*0xFFFFu + (uhi & 2u)*0x7FFF8000u;
                P0[1][nt] = ex2_f16x2(pack_f16x2(s[0], s[1])) & mwlo;
                P1[1][nt] = ex2_f16x2(pack_f16x2(s[2], s[3])) & mwhi;
            }
        }

        const uint32_t vpb = vp_lane + buf*(VP_WORDS*4);
        #pragma unroll
        for (int hf = 0; hf < 2; hf++) {
            uint32_t aA[2][4], aB[2][4];
            #pragma unroll
            for (int j = 0; j < 2; j++) {
                aA[j][0] = P0[j][4*hf    ]; aA[j][1] = P1[j][4*hf    ];
                aA[j][2] = P0[j][4*hf + 1]; aA[j][3] = P1[j][4*hf + 1];
                aB[j][0] = P0[j][4*hf + 2]; aB[j][1] = P1[j][4*hf + 2];
                aB[j][2] = P0[j][4*hf + 3]; aB[j][3] = P1[j][4*hf + 3];
                mma16816h(o4[j], aA[j], ones, ones);
                mma16816h(o4[j], aB[j], ones, ones);
            }
            #pragma unroll
            for (int dt = 0; dt < 4; dt++) {
                uint32_t vb0, vb1, vb2, vb3;
                ldmx4(vb0, vb1, vb2, vb3, vpb + dt*(8*VP_STRIDE*4) + hf*64);
                #pragma unroll
                for (int j = 0; j < 2; j++) {
                    mma16816h(o[j][dt], aA[j], vb0, vb1);
                    mma16816h(o[j][dt], aB[j], vb2, vb3);
                }
            }
        }
    };

    for (int kt = 0; kt < SEQ/64; kt += 2) {
        tile_body(kt,     kvA, v0A, v1A, mskA);
        tile_body(kt + 1, kvB, v0B, v1B, mskB);
    }

    const int n_  = b*NHEAD + h;
    const int bo  = n_ & 3;
    const int hp  = n_ >> 2;
    #pragma unroll
    for (int j = 0; j < 2; j++) {
        const float sum_lo = __shfl_sync(0xffffffffu, o4[j][0], lane & ~3);
        const float sum_hi = __shfl_sync(0xffffffffu, o4[j][2], lane & ~3);
        const float inv_lo = 1.f / sum_lo;
        const float inv_hi = 1.f / sum_hi;
        #pragma unroll
        for (int dt = 0; dt < 4; dt++) {
            const size_t base = ((size_t)(bo*SEQ + q0 + gr + 16*j))*DIM
                                + hp*HDIM + dt*8 + c2;
            *(uint32_t*)&outp[base] =
                pack_bf16x2(o[j][dt][0]*inv_lo, o[j][dt][1]*inv_lo);
            *(uint32_t*)&outp[base + 8*DIM] =
                pack_bf16x2(o[j][dt][2]*inv_hi, o[j][dt][3]*inv_hi);
        }
    }
}

// ---------------------------------------------------------------------------
extern "C" void kernel_launch(void* const* d_in, const int* in_sizes, int n_in,
                              void* d_out, int out_size)
{
    const float* x     = (const float*)d_in[0];
    const int*   adj   = (const int*)  d_in[1];
    const float* w_qkv = (const float*)d_in[2];
    const float* b_qkv = (const float*)d_in[3];
    const float* ln_g  = (const float*)d_in[4];
    const float* ln_b  = (const float*)d_in[5];
    const float* w_fc  = (const float*)d_in[6];
    const float* b_fc  = (const float*)d_in[7];
    const float* w_z   = (const float*)d_in[8];
    const float* b_z   = (const float*)d_in[9];
    const float* u_z   = (const float*)d_in[10];
    const float* w_r   = (const float*)d_in[11];
    const float* u_r   = (const float*)d_in[12];
    const float* w_g   = (const float*)d_in[13];
    const float* u_g   = (const float*)d_in[14];
    float* out = (float*)d_out;

    __nv_bfloat16 *xn, *xt, *att, *y, *rx, *wt, *qb, *kb;
    float *z;
    __half *vb;
    uint32_t *mask;
    cudaGetSymbolAddress((void**)&xn,   g_xn);
    cudaGetSymbolAddress((void**)&xt,   g_xt);
    cudaGetSymbolAddress((void**)&att,  g_att);
    cudaGetSymbolAddress((void**)&y,    g_y);
    cudaGetSymbolAddress((void**)&z,    g_z);
    cudaGetSymbolAddress((void**)&rx,   g_rx);
    cudaGetSymbolAddress((void**)&wt,   g_wt);
    cudaGetSymbolAddress((void**)&qb,   g_q);
    cudaGetSymbolAddress((void**)&kb,   g_k);
    cudaGetSymbolAddress((void**)&vb,   g_v);
    cudaGetSymbolAddress((void**)&mask, g_mask);

    static bool init = false;
    if (!init) {
        cudaFuncSetAttribute(gemm_tc, cudaFuncAttributeMaxDynamicSharedMemorySize, GSMEM);
        init = true;
    }

    // 0. fused preamble: pack_adj + wconv + LayerNorm in one launch
    preamble<<<NPRE, 256>>>(adj, mask,
                            w_qkv, w_fc, w_z, u_z, w_r, u_r, w_g, u_g, wt,
                            x, ln_g, ln_b, xn, xt);
    // 1. QKV -> q/k/v (bf16/bf16/fp16, q log2-prescaled)
    gemm_tc<<<dim3(12, 64), 256, GSMEM>>>(xn, nullptr, wt + OFF_QKV, nullptr,
                                          nullptr, nullptr, b_qkv, nullptr, nullptr,
                                          nullptr, nullptr, qb, kb, vb, MODE_QKV, 4);
    // 2. flash attention -> bf16 att
    attn_mma<<<dim3(SEQ/256, NHEAD, BATCH), 256>>>(qb, kb, vb, mask, att);
    // 3. FC + ReLU -> bf16 y
    gemm_tc<<<dim3(4, 64), 256, GSMEM>>>(att, nullptr, wt + OFF_FC, nullptr,
                                         nullptr, nullptr, b_fc, nullptr, nullptr,
                                         nullptr, y, nullptr, nullptr, nullptr, MODE_FC, 4);
    // 4. fused ZR -> fp32 z, bf16 rx
    gemm_tc<<<dim3(8, 64), 256, GSMEM>>>(y, xt, wt + OFF_WZ, wt + OFF_UZ,
                                         wt + OFF_WR, wt + OFF_UR, b_z, x, nullptr,
                                         z, rx, nullptr, nullptr, nullptr, MODE_ZR, 8);
    // 5. H -> fp32 out
    gemm_tc<<<dim3(4, 64), 256, GSMEM>>>(y, rx, wt + OFF_WG, wt + OFF_UG,
                                         nullptr, nullptr, nullptr, x, z,
                                         out, nullptr, nullptr, nullptr, nullptr, MODE_H, 8);
}